// round 6
// baseline (speedup 1.0000x reference)
#include <cuda_runtime.h>
#include <cstdint>

// Embedding gather via per-lane TMA bulk copies (sm_103a).
// x: [32768] int32; emb: [50257, 512] f32; out: [32768, 512] f32.
// even ids -> id 0 (reference: jnp.where(x % 2 == 0, 0, x)).
//
// R4's TMA version was serial (one thread looping rows -> tma pipe 2.2%).
// Here every row gets its OWN lane, smem slot, and mbarrier:
//   lane l: UBLKCP gmem->smem[l] -> mbarrier wait -> UBLKCP smem[l]->gmem
// 16 independent async chains per CTA, ~6-7 CTAs/SM => >100 rows in flight
// per SM, all bytes on the TMA/LTS path, none through L1tex/registers.

static constexpr int ROW_BYTES    = 2048;
static constexpr int ROWS_PER_CTA = 16;
static constexpr int THREADS      = 32;

__device__ __forceinline__ uint32_t smem_u32(const void* p) {
    return (uint32_t)__cvta_generic_to_shared(p);
}

__global__ __launch_bounds__(THREADS)
void embed_tma_kernel(const int* __restrict__ x,
                      const char* __restrict__ emb,
                      char* __restrict__ out,
                      int n_rows) {
    __shared__ alignas(128) char buf[ROWS_PER_CTA][ROW_BYTES];
    __shared__ alignas(8) unsigned long long mbar[ROWS_PER_CTA];

    const int lane = threadIdx.x;
    const int base = blockIdx.x * ROWS_PER_CTA;

    if (lane >= ROWS_PER_CTA) return;

    const int r = base + lane;
    const bool valid = (r < n_rows);

    // Token id load overlaps with mbarrier init.
    int tok = valid ? x[r] : 0;
    tok = (tok & 1) ? tok : 0;          // even ids -> row 0

    const uint32_t mb  = smem_u32(&mbar[lane]);
    const uint32_t sl  = smem_u32(&buf[lane][0]);

    asm volatile("mbarrier.init.shared.b64 [%0], 1;" :: "r"(mb) : "memory");
    // Order the generic-proxy init before async-proxy (TMA) use; same thread.
    asm volatile("fence.proxy.async.shared::cta;" ::: "memory");

    if (!valid) return;

    // expect_tx carries the single arrival + transaction count.
    asm volatile("mbarrier.arrive.expect_tx.shared.b64 _, [%0], %1;"
                 :: "r"(mb), "n"(ROW_BYTES) : "memory");

    const char* src = emb + (size_t)tok * ROW_BYTES;
    asm volatile(
        "cp.async.bulk.shared::cta.global.mbarrier::complete_tx::bytes "
        "[%0], [%1], %2, [%3];"
        :: "r"(sl), "l"(src), "n"(ROW_BYTES), "r"(mb) : "memory");

    // Wait for this lane's row to land (parity 0, single use).
    asm volatile(
        "{\n\t"
        ".reg .pred P1;\n\t"
        "WAIT_LOOP_%=:\n\t"
        "mbarrier.try_wait.parity.acquire.cta.shared::cta.b64 P1, [%0], 0, 0x989680;\n\t"
        "@P1 bra.uni WAIT_DONE_%=;\n\t"
        "bra.uni WAIT_LOOP_%=;\n\t"
        "WAIT_DONE_%=:\n\t"
        "}"
        :: "r"(mb) : "memory");

    char* dst = out + (size_t)r * ROW_BYTES;
    asm volatile(
        "cp.async.bulk.global.shared::cta.bulk_group [%0], [%1], %2;"
        :: "l"(dst), "r"(sl), "n"(ROW_BYTES) : "memory");
    asm volatile("cp.async.bulk.commit_group;" ::: "memory");
    // Full completion (not just .read) so the write is done before CTA exit.
    asm volatile("cp.async.bulk.wait_group 0;" ::: "memory");
}

extern "C" void kernel_launch(void* const* d_in, const int* in_sizes, int n_in,
                              void* d_out, int out_size) {
    const int* x    = (const int*)d_in[0];
    const char* emb = (const char*)d_in[1];
    char* out       = (char*)d_out;

    int n_rows   = in_sizes[0];                                   // 32768
    int n_blocks = (n_rows + ROWS_PER_CTA - 1) / ROWS_PER_CTA;    // 2048

    embed_tma_kernel<<<n_blocks, THREADS>>>(x, emb, out, n_rows);
}